// round 7
// baseline (speedup 1.0000x reference)
#include <cuda_runtime.h>
#include <cuda_bf16.h>
#include <math.h>
#include <limits.h>

// Problem constants (fixed by the reference)
#define N_NODES    12288
#define N_FEATURES 256
#define KEY_DIM    128
#define N_GRAPHS   192
#define QKV_COLS   512        // [Q(128) | K(128) | V(256)]

// Scratch: QKV projections, 12288 x 512 fp32 = 25.2 MB (static __device__, no allocs)
__device__ float g_QKV[N_NODES * QKV_COLS];
__device__ int   g_start[N_GRAPHS];
__device__ int   g_end[N_GRAPHS];

// ---------------------------------------------------------------------------
// Kernel 0: init per-graph ranges
// ---------------------------------------------------------------------------
__global__ void init_ranges_kernel() {
    int g = blockIdx.x * blockDim.x + threadIdx.x;
    if (g < N_GRAPHS) {
        g_start[g] = INT_MAX;
        g_end[g]   = 0;
    }
}

// ---------------------------------------------------------------------------
// Kernel 1: compute per-graph [start, end) from sorted batch array.
// Robust to the batch buffer actually holding int32 (JAX x64-disabled
// silently downcasts jnp.int64): probe one int64 mid-array; if the value is
// out of [0, N_GRAPHS) the high 32 bits were a second element -> int32 data.
// Probe index N_NODES/4 stays in-bounds for both interpretations.
// ---------------------------------------------------------------------------
__global__ void compute_ranges_kernel(const void* __restrict__ batch) {
    int i = blockIdx.x * blockDim.x + threadIdx.x;
    if (i >= N_NODES) return;
    const long long* b64 = (const long long*)batch;
    long long probe = b64[N_NODES / 4];
    bool is32 = (probe < 0) || (probe >= (long long)N_GRAPHS);
    int g = is32 ? ((const int*)batch)[i] : (int)b64[i];
    if (g < 0 || g >= N_GRAPHS) return;   // defensive
    atomicMin(&g_start[g], i);
    atomicMax(&g_end[g], i + 1);
}

// ---------------------------------------------------------------------------
// Kernel 2: fused QKV projection GEMM.
//   QKV[N, 512] = X[N, 256] @ [Wq | Wk | Wv]   (all fp32)
// Tiling: BM=64, BN=128, BK=32, 256 threads, per-thread 8x4 micro-tile.
// grid.x selects the weight slab: 0->Wq, 1->Wk, 2->Wv[:,0:128], 3->Wv[:,128:256]
// ---------------------------------------------------------------------------
#define GB_M 64
#define GB_N 128
#define GB_K 32
#define GB_MPAD 65

__global__ __launch_bounds__(256)
void qkv_gemm_kernel(const float* __restrict__ X,
                     const float* __restrict__ Wq,
                     const float* __restrict__ Wk,
                     const float* __restrict__ Wv) {
    __shared__ float As[GB_K * GB_MPAD];   // transposed A tile, padded
    __shared__ float Bs[GB_K * GB_N];

    const int bx = blockIdx.x;   // 0..3
    const int by = blockIdx.y;   // 0..191

    const float* W;
    int ldw, ncol0;
    if (bx == 0)      { W = Wq; ldw = KEY_DIM;    ncol0 = 0;   }
    else if (bx == 1) { W = Wk; ldw = KEY_DIM;    ncol0 = 0;   }
    else              { W = Wv; ldw = N_FEATURES; ncol0 = (bx - 2) * 128; }

    const int tid  = threadIdx.x;
    const int ty   = tid >> 5;        // 0..7   -> row group (8 rows each)
    const int tx   = tid & 31;        // 0..31  -> col group (4 cols each)
    const int row0 = by * GB_M;

    float acc[8][4];
#pragma unroll
    for (int r = 0; r < 8; r++)
#pragma unroll
        for (int c = 0; c < 4; c++) acc[r][c] = 0.0f;

    for (int k0 = 0; k0 < N_FEATURES; k0 += GB_K) {
        // Load A tile 64x32 (transposed into smem)
#pragma unroll
        for (int t = tid; t < (GB_M * GB_K) / 4; t += 256) {
            int r = t >> 3;            // 0..63
            int c = (t & 7) << 2;      // 0,4,...,28
            float4 v = *(const float4*)&X[(row0 + r) * N_FEATURES + k0 + c];
            As[(c + 0) * GB_MPAD + r] = v.x;
            As[(c + 1) * GB_MPAD + r] = v.y;
            As[(c + 2) * GB_MPAD + r] = v.z;
            As[(c + 3) * GB_MPAD + r] = v.w;
        }
        // Load B tile 32x128
#pragma unroll
        for (int t = tid; t < (GB_K * GB_N) / 4; t += 256) {
            int r = t >> 5;            // 0..31
            int c = (t & 31) << 2;     // 0..124
            float4 v = *(const float4*)&W[(k0 + r) * ldw + ncol0 + c];
            *(float4*)&Bs[r * GB_N + c] = v;
        }
        __syncthreads();

#pragma unroll
        for (int k = 0; k < GB_K; k++) {
            float a[8];
#pragma unroll
            for (int r = 0; r < 8; r++) a[r] = As[k * GB_MPAD + ty * 8 + r];
            float4 bv = *(const float4*)&Bs[k * GB_N + tx * 4];
            float b[4] = {bv.x, bv.y, bv.z, bv.w};
#pragma unroll
            for (int r = 0; r < 8; r++)
#pragma unroll
                for (int c = 0; c < 4; c++) acc[r][c] += a[r] * b[c];
        }
        __syncthreads();
    }

    const int col0 = bx * 128 + tx * 4;
#pragma unroll
    for (int r = 0; r < 8; r++) {
        float4 v = make_float4(acc[r][0], acc[r][1], acc[r][2], acc[r][3]);
        *(float4*)&g_QKV[(row0 + ty * 8 + r) * QKV_COLS + col0] = v;
    }
}

// ---------------------------------------------------------------------------
// Kernel 3: per-graph attention pooling.
// One CTA (256 threads = 8 warps) per graph.
//   w[j] = sum_i softmax_row_i(QK^T/16)[j]   (column sums of the softmax)
//   out[g, f] = sum_j w[j] * V[j, f]
// K tile cached in smem with row stride 129 (conflict-free lane-per-j dot).
// Warp-per-row; per-warp colsum partials (deterministic, no atomics).
// ---------------------------------------------------------------------------
#define NGMAX 128
#define KPAD  129
#define ATTN_SMEM_FLOATS (NGMAX * KPAD + 8 * NGMAX + 8 * KEY_DIM + NGMAX)
#define ATTN_SMEM_BYTES  (ATTN_SMEM_FLOATS * 4)

__global__ __launch_bounds__(256)
void attn_pool_kernel(float* __restrict__ out) {
    extern __shared__ float sm[];
    float* sK     = sm;                             // NGMAX * KPAD
    float* wcol   = sK + NGMAX * KPAD;              // 8 * NGMAX
    float* sQ     = wcol + 8 * NGMAX;               // 8 * 128
    float* colsum = sQ + 8 * KEY_DIM;               // NGMAX

    const int g    = blockIdx.x;
    const int tid  = threadIdx.x;
    const int w    = tid >> 5;
    const int lane = tid & 31;

    int s = g_start[g];
    int e = g_end[g];
    int n = e - s;

    if (n <= 0) {                 // empty graph -> zeros
        out[g * N_FEATURES + tid] = 0.0f;
        return;
    }
    if (n > NGMAX) n = NGMAX;     // statistically unreachable (mean 64, max ~90)

    // Stage K rows into smem (padded stride)
    for (int t = tid; t < n * KEY_DIM; t += 256) {
        int j = t >> 7;
        int k = t & 127;
        sK[j * KPAD + k] = g_QKV[(s + j) * QKV_COLS + KEY_DIM + k];
    }
    for (int t = tid; t < 8 * NGMAX; t += 256) wcol[t] = 0.0f;
    __syncthreads();

    // One row per warp, round-robin
    for (int i = w; i < n; i += 8) {
        __syncwarp();
        // load Q row into this warp's smem slot
        for (int k = lane; k < KEY_DIM; k += 32)
            sQ[w * KEY_DIM + k] = g_QKV[(s + i) * QKV_COLS + k];
        __syncwarp();

        float sc[(NGMAX + 31) / 32];
        float m = -INFINITY;
        int nj = 0;
        for (int j = lane; j < n; j += 32) {
            const float* kr = &sK[j * KPAD];
            const float* qr = &sQ[w * KEY_DIM];
            float d = 0.0f;
#pragma unroll 16
            for (int k = 0; k < KEY_DIM; k++) d += qr[k] * kr[k];
            d *= 0.0625f;                       // / sqrt(256)
            sc[nj++] = d;
            m = fmaxf(m, d);
        }
#pragma unroll
        for (int o = 16; o > 0; o >>= 1) m = fmaxf(m, __shfl_xor_sync(0xffffffffu, m, o));
        float ssum = 0.0f;
        for (int q = 0; q < nj; q++) { sc[q] = __expf(sc[q] - m); ssum += sc[q]; }
#pragma unroll
        for (int o = 16; o > 0; o >>= 1) ssum += __shfl_xor_sync(0xffffffffu, ssum, o);
        const float inv = 1.0f / ssum;
        nj = 0;
        for (int j = lane; j < n; j += 32) wcol[w * NGMAX + j] += sc[nj++] * inv;
    }
    __syncthreads();

    // Reduce per-warp colsum partials
    for (int j = tid; j < n; j += 256) {
        float t = 0.0f;
#pragma unroll
        for (int ww = 0; ww < 8; ww++) t += wcol[ww * NGMAX + j];
        colsum[j] = t;
    }
    __syncthreads();

    // Weighted sum of V rows; thread = feature (coalesced)
    const int f = tid;
    float acc = 0.0f;
    for (int j = 0; j < n; j++)
        acc += colsum[j] * g_QKV[(s + j) * QKV_COLS + 2 * KEY_DIM + f];
    out[g * N_FEATURES + f] = acc;
}

// ---------------------------------------------------------------------------
// Launch
// ---------------------------------------------------------------------------
extern "C" void kernel_launch(void* const* d_in, const int* in_sizes, int n_in,
                              void* d_out, int out_size) {
    const float* X  = (const float*)d_in[0];
    const void*  batch = d_in[1];
    const float* Wq = (const float*)d_in[2];
    const float* Wk = (const float*)d_in[3];
    const float* Wv = (const float*)d_in[4];
    float* out = (float*)d_out;

    cudaFuncSetAttribute(attn_pool_kernel,
                         cudaFuncAttributeMaxDynamicSharedMemorySize,
                         ATTN_SMEM_BYTES);

    init_ranges_kernel<<<1, N_GRAPHS>>>();
    compute_ranges_kernel<<<(N_NODES + 255) / 256, 256>>>(batch);
    qkv_gemm_kernel<<<dim3(4, N_NODES / GB_M), 256>>>(X, Wq, Wk, Wv);
    attn_pool_kernel<<<N_GRAPHS, 256, ATTN_SMEM_BYTES>>>(out);
}

// round 8
// speedup vs baseline: 1.0945x; 1.0945x over previous
#include <cuda_runtime.h>
#include <cuda_bf16.h>
#include <math.h>
#include <limits.h>

// Problem constants (fixed by the reference)
#define N_NODES    12288
#define N_FEATURES 256
#define KEY_DIM    128
#define N_GRAPHS   192
#define QKV_COLS   512        // [Q(128) | K(128) | V(256)]

typedef unsigned long long ull;

// Packed fp32x2 ops (Blackwell sm_103a; ptxas never emits FFMA2 from C++)
__device__ __forceinline__ void ffma2(ull& d, ull a, ull b) {
    asm("fma.rn.f32x2 %0, %1, %2, %0;" : "+l"(d) : "l"(a), "l"(b));
}
__device__ __forceinline__ ull pack2(float lo, float hi) {
    ull r; asm("mov.b64 %0, {%1, %2};" : "=l"(r) : "f"(lo), "f"(hi)); return r;
}
__device__ __forceinline__ float2 unpack2(ull v) {
    float2 r; asm("mov.b64 {%0, %1}, %2;" : "=f"(r.x), "=f"(r.y) : "l"(v)); return r;
}
__device__ __forceinline__ ull addx2(ull a, ull b) {
    ull r; asm("add.rn.f32x2 %0, %1, %2;" : "=l"(r) : "l"(a), "l"(b)); return r;
}

// Scratch: QKV projections, 12288 x 512 fp32 = 25.2 MB (static __device__, no allocs)
__device__ float g_QKV[N_NODES * QKV_COLS];
__device__ int   g_start[N_GRAPHS];
__device__ int   g_end[N_GRAPHS];

// ---------------------------------------------------------------------------
// Kernel 0: init per-graph ranges
// ---------------------------------------------------------------------------
__global__ void init_ranges_kernel() {
    int g = blockIdx.x * blockDim.x + threadIdx.x;
    if (g < N_GRAPHS) {
        g_start[g] = INT_MAX;
        g_end[g]   = 0;
    }
}

// ---------------------------------------------------------------------------
// Kernel 1: per-graph [start, end) from sorted batch (robust to int32/int64)
// ---------------------------------------------------------------------------
__global__ void compute_ranges_kernel(const void* __restrict__ batch) {
    int i = blockIdx.x * blockDim.x + threadIdx.x;
    if (i >= N_NODES) return;
    const long long* b64 = (const long long*)batch;
    long long probe = b64[N_NODES / 4];
    bool is32 = (probe < 0) || (probe >= (long long)N_GRAPHS);
    int g = is32 ? ((const int*)batch)[i] : (int)b64[i];
    if (g < 0 || g >= N_GRAPHS) return;   // defensive
    atomicMin(&g_start[g], i);
    atomicMax(&g_end[g], i + 1);
}

// ---------------------------------------------------------------------------
// Kernel 2: fused QKV projection GEMM with packed fp32x2 FMAs.
//   QKV[N, 512] = X[N, 256] @ [Wq | Wk | Wv]   (all fp32)
// BM=64, BN=128, BK=32, 256 threads, per-thread 8x4 micro-tile computed as
// 4 row-pairs x 4 cols of FFMA2 (A row-pairs come straight out of the
// k-major smem tile as aligned 8B loads; B scalars packed-duplicated).
// ---------------------------------------------------------------------------
#define GB_M 64
#define GB_N 128
#define GB_K 32
#define GB_MPAD 66     // even -> 8B-aligned row-pair loads

__global__ __launch_bounds__(256)
void qkv_gemm_kernel(const float* __restrict__ X,
                     const float* __restrict__ Wq,
                     const float* __restrict__ Wk,
                     const float* __restrict__ Wv) {
    __shared__ float As[GB_K * GB_MPAD];   // transposed A tile (k-major), padded
    __shared__ float Bs[GB_K * GB_N];

    const int bx = blockIdx.x;   // 0..3 weight slab
    const int by = blockIdx.y;   // 0..191

    const float* W;
    int ldw, ncol0;
    if (bx == 0)      { W = Wq; ldw = KEY_DIM;    ncol0 = 0;   }
    else if (bx == 1) { W = Wk; ldw = KEY_DIM;    ncol0 = 0;   }
    else              { W = Wv; ldw = N_FEATURES; ncol0 = (bx - 2) * 128; }

    const int tid  = threadIdx.x;
    const int ty   = tid >> 5;        // 0..7   -> row group (8 rows)
    const int tx   = tid & 31;        // 0..31  -> col group (4 cols)
    const int row0 = by * GB_M;

    ull acc2[4][4];                   // [row-pair][col], each holds 2 rows
#pragma unroll
    for (int rp = 0; rp < 4; rp++)
#pragma unroll
        for (int c = 0; c < 4; c++) acc2[rp][c] = 0ull;

    for (int k0 = 0; k0 < N_FEATURES; k0 += GB_K) {
        // A tile 64x32, transposed into k-major smem
#pragma unroll
        for (int t = tid; t < (GB_M * GB_K) / 4; t += 256) {
            int r = t >> 3;            // 0..63
            int c = (t & 7) << 2;      // 0,4,...,28
            float4 v = *(const float4*)&X[(row0 + r) * N_FEATURES + k0 + c];
            As[(c + 0) * GB_MPAD + r] = v.x;
            As[(c + 1) * GB_MPAD + r] = v.y;
            As[(c + 2) * GB_MPAD + r] = v.z;
            As[(c + 3) * GB_MPAD + r] = v.w;
        }
        // B tile 32x128
#pragma unroll
        for (int t = tid; t < (GB_K * GB_N) / 4; t += 256) {
            int r = t >> 5;
            int c = (t & 31) << 2;
            float4 v = *(const float4*)&W[(k0 + r) * ldw + ncol0 + c];
            *(float4*)&Bs[r * GB_N + c] = v;
        }
        __syncthreads();

#pragma unroll
        for (int k = 0; k < GB_K; k++) {
            const ull* arow = (const ull*)&As[k * GB_MPAD + ty * 8]; // 8B-aligned
            ull a2[4];
#pragma unroll
            for (int rp = 0; rp < 4; rp++) a2[rp] = arow[rp];        // LDS.64 broadcast
            float4 bv = *(const float4*)&Bs[k * GB_N + tx * 4];
            ull bd[4] = { pack2(bv.x, bv.x), pack2(bv.y, bv.y),
                          pack2(bv.z, bv.z), pack2(bv.w, bv.w) };
#pragma unroll
            for (int rp = 0; rp < 4; rp++)
#pragma unroll
                for (int c = 0; c < 4; c++) ffma2(acc2[rp][c], a2[rp], bd[c]);
        }
        __syncthreads();
    }

    const int col0 = bx * 128 + tx * 4;
#pragma unroll
    for (int rp = 0; rp < 4; rp++) {
        float2 p0 = unpack2(acc2[rp][0]);
        float2 p1 = unpack2(acc2[rp][1]);
        float2 p2 = unpack2(acc2[rp][2]);
        float2 p3 = unpack2(acc2[rp][3]);
        int re = row0 + ty * 8 + 2 * rp;
        *(float4*)&g_QKV[re * QKV_COLS + col0]       = make_float4(p0.x, p1.x, p2.x, p3.x);
        *(float4*)&g_QKV[(re + 1) * QKV_COLS + col0] = make_float4(p0.y, p1.y, p2.y, p3.y);
    }
}

// ---------------------------------------------------------------------------
// Kernel 3: per-graph attention pooling, fp32x2 dot products.
// One CTA (256 threads = 8 warps) per graph.
//   w[j] = sum_i softmax_row_i(QK^T/16)[j]   (column sums of the softmax)
//   out[g, f] = sum_j w[j] * V[j, f]
// ---------------------------------------------------------------------------
#define NGMAX 128
#define KPAD  130      // even: 8B-aligned pair loads; 2j+k banks conflict-free
#define ATTN_SMEM_FLOATS (NGMAX * KPAD + 8 * NGMAX + 8 * KEY_DIM + NGMAX)
#define ATTN_SMEM_BYTES  (ATTN_SMEM_FLOATS * 4)

__global__ __launch_bounds__(256)
void attn_pool_kernel(float* __restrict__ out) {
    extern __shared__ float sm[];
    float* sK     = sm;                             // NGMAX * KPAD
    float* wcol   = sK + NGMAX * KPAD;              // 8 * NGMAX
    float* sQ     = wcol + 8 * NGMAX;               // 8 * 128
    float* colsum = sQ + 8 * KEY_DIM;               // NGMAX

    const int g    = blockIdx.x;
    const int tid  = threadIdx.x;
    const int w    = tid >> 5;
    const int lane = tid & 31;

    int s = g_start[g];
    int e = g_end[g];
    int n = e - s;

    if (n <= 0) {                 // empty graph -> zeros
        out[g * N_FEATURES + tid] = 0.0f;
        return;
    }
    if (n > NGMAX) n = NGMAX;     // unreachable (binomial mean 64, max ~90)

    // Stage K rows into smem: float4 gmem reads, float2 smem stores
    for (int t = tid; t < n * (KEY_DIM / 4); t += 256) {
        int j = t >> 5;
        int k = (t & 31) << 2;
        float4 v = *(const float4*)&g_QKV[(s + j) * QKV_COLS + KEY_DIM + k];
        *(float2*)&sK[j * KPAD + k]     = make_float2(v.x, v.y);
        *(float2*)&sK[j * KPAD + k + 2] = make_float2(v.z, v.w);
    }
    for (int t = tid; t < 8 * NGMAX; t += 256) wcol[t] = 0.0f;
    __syncthreads();

    // One row per warp, round-robin
    for (int i = w; i < n; i += 8) {
        __syncwarp();
        // load Q row (128 floats = 32 lanes x float4)
        {
            float4 v = *(const float4*)&g_QKV[(s + i) * QKV_COLS + lane * 4];
            *(float4*)&sQ[w * KEY_DIM + lane * 4] = v;
        }
        __syncwarp();

        const ull* q2 = (const ull*)&sQ[w * KEY_DIM];

        float sc[(NGMAX + 31) / 32];
        float m = -INFINITY;
        int nj = 0;
        for (int j = lane; j < n; j += 32) {
            const ull* k2 = (const ull*)&sK[j * KPAD];
            ull a0 = 0, a1 = 0, a2v = 0, a3 = 0;
#pragma unroll
            for (int kk = 0; kk < KEY_DIM / 2; kk += 4) {
                ffma2(a0,  q2[kk + 0], k2[kk + 0]);
                ffma2(a1,  q2[kk + 1], k2[kk + 1]);
                ffma2(a2v, q2[kk + 2], k2[kk + 2]);
                ffma2(a3,  q2[kk + 3], k2[kk + 3]);
            }
            float2 t2 = unpack2(addx2(addx2(a0, a1), addx2(a2v, a3)));
            float d = (t2.x + t2.y) * 0.0625f;       // / sqrt(256)
            sc[nj++] = d;
            m = fmaxf(m, d);
        }
#pragma unroll
        for (int o = 16; o > 0; o >>= 1) m = fmaxf(m, __shfl_xor_sync(0xffffffffu, m, o));
        float ssum = 0.0f;
        for (int q = 0; q < nj; q++) { sc[q] = __expf(sc[q] - m); ssum += sc[q]; }
#pragma unroll
        for (int o = 16; o > 0; o >>= 1) ssum += __shfl_xor_sync(0xffffffffu, ssum, o);
        const float inv = 1.0f / ssum;
        nj = 0;
        for (int j = lane; j < n; j += 32) wcol[w * NGMAX + j] += sc[nj++] * inv;
    }
    __syncthreads();

    // Reduce per-warp colsum partials (deterministic)
    for (int j = tid; j < n; j += 256) {
        float t = 0.0f;
#pragma unroll
        for (int ww = 0; ww < 8; ww++) t += wcol[ww * NGMAX + j];
        colsum[j] = t;
    }
    __syncthreads();

    // Weighted sum of V rows; thread = feature (coalesced 1KB rows)
    const int f = tid;
    float acc = 0.0f;
#pragma unroll 4
    for (int j = 0; j < n; j++)
        acc += colsum[j] * g_QKV[(s + j) * QKV_COLS + 2 * KEY_DIM + f];
    out[g * N_FEATURES + f] = acc;
}

// ---------------------------------------------------------------------------
// Launch
// ---------------------------------------------------------------------------
extern "C" void kernel_launch(void* const* d_in, const int* in_sizes, int n_in,
                              void* d_out, int out_size) {
    const float* X  = (const float*)d_in[0];
    const void*  batch = d_in[1];
    const float* Wq = (const float*)d_in[2];
    const float* Wk = (const float*)d_in[3];
    const float* Wv = (const float*)d_in[4];
    float* out = (float*)d_out;

    cudaFuncSetAttribute(attn_pool_kernel,
                         cudaFuncAttributeMaxDynamicSharedMemorySize,
                         ATTN_SMEM_BYTES);

    init_ranges_kernel<<<1, N_GRAPHS>>>();
    compute_ranges_kernel<<<(N_NODES + 255) / 256, 256>>>(batch);
    qkv_gemm_kernel<<<dim3(4, N_NODES / GB_M), 256>>>(X, Wq, Wk, Wv);
    attn_pool_kernel<<<N_GRAPHS, 256, ATTN_SMEM_BYTES>>>(out);
}

// round 9
// speedup vs baseline: 1.1506x; 1.0513x over previous
#include <cuda_runtime.h>
#include <cuda_bf16.h>
#include <math.h>
#include <limits.h>

// Problem constants (fixed by the reference)
#define N_NODES    12288
#define N_FEATURES 256
#define KEY_DIM    128
#define N_GRAPHS   192
#define QKV_COLS   512        // [Q(128) | K(128) | V(256)]

#define SPLIT 4               // row-split CTAs per graph for the score phase
#define NGMAX 128
#define KPAD  130             // even: 8B-aligned pair loads; 65-ull stride -> conflict-free

typedef unsigned long long ull;

// Packed fp32x2 ops (Blackwell sm_103a; ptxas never emits FFMA2 from C++)
__device__ __forceinline__ void ffma2(ull& d, ull a, ull b) {
    asm("fma.rn.f32x2 %0, %1, %2, %0;" : "+l"(d) : "l"(a), "l"(b));
}
__device__ __forceinline__ ull pack2(float lo, float hi) {
    ull r; asm("mov.b64 %0, {%1, %2};" : "=l"(r) : "f"(lo), "f"(hi)); return r;
}
__device__ __forceinline__ float2 unpack2(ull v) {
    float2 r; asm("mov.b64 {%0, %1}, %2;" : "=f"(r.x), "=f"(r.y) : "l"(v)); return r;
}
__device__ __forceinline__ ull addx2(ull a, ull b) {
    ull r; asm("add.rn.f32x2 %0, %1, %2;" : "=l"(r) : "l"(a), "l"(b)); return r;
}

// Static device scratch (no allocs)
__device__ float g_QKV[N_NODES * QKV_COLS];              // 25.2 MB
__device__ float g_wpart[SPLIT * N_GRAPHS * NGMAX];      // 384 KB partial colsums
__device__ int   g_start[N_GRAPHS];
__device__ int   g_end[N_GRAPHS];

// ---------------------------------------------------------------------------
// Kernel 0: init per-graph ranges
// ---------------------------------------------------------------------------
__global__ void init_ranges_kernel() {
    int g = blockIdx.x * blockDim.x + threadIdx.x;
    if (g < N_GRAPHS) {
        g_start[g] = INT_MAX;
        g_end[g]   = 0;
    }
}

// ---------------------------------------------------------------------------
// Kernel 1: per-graph [start, end) from sorted batch (robust to int32/int64)
// ---------------------------------------------------------------------------
__global__ void compute_ranges_kernel(const void* __restrict__ batch) {
    int i = blockIdx.x * blockDim.x + threadIdx.x;
    if (i >= N_NODES) return;
    const long long* b64 = (const long long*)batch;
    long long probe = b64[N_NODES / 4];
    bool is32 = (probe < 0) || (probe >= (long long)N_GRAPHS);
    int g = is32 ? ((const int*)batch)[i] : (int)b64[i];
    if (g < 0 || g >= N_GRAPHS) return;   // defensive
    atomicMin(&g_start[g], i);
    atomicMax(&g_end[g], i + 1);
}

// ---------------------------------------------------------------------------
// Kernel 2: fused QKV projection GEMM with packed fp32x2 FMAs.
//   QKV[N, 512] = X[N, 256] @ [Wq | Wk | Wv]   (all fp32)
// BM=64, BN=128, BK=32, 256 threads, 8x4 micro-tile as 4 row-pairs of FFMA2.
// ---------------------------------------------------------------------------
#define GB_M 64
#define GB_N 128
#define GB_K 32
#define GB_MPAD 66     // even -> 8B-aligned row-pair loads

__global__ __launch_bounds__(256)
void qkv_gemm_kernel(const float* __restrict__ X,
                     const float* __restrict__ Wq,
                     const float* __restrict__ Wk,
                     const float* __restrict__ Wv) {
    __shared__ float As[GB_K * GB_MPAD];   // transposed A tile (k-major), padded
    __shared__ float Bs[GB_K * GB_N];

    const int bx = blockIdx.x;   // 0..3 weight slab
    const int by = blockIdx.y;   // 0..191

    const float* W;
    int ldw, ncol0;
    if (bx == 0)      { W = Wq; ldw = KEY_DIM;    ncol0 = 0;   }
    else if (bx == 1) { W = Wk; ldw = KEY_DIM;    ncol0 = 0;   }
    else              { W = Wv; ldw = N_FEATURES; ncol0 = (bx - 2) * 128; }

    const int tid  = threadIdx.x;
    const int ty   = tid >> 5;        // 0..7   -> row group (8 rows)
    const int tx   = tid & 31;        // 0..31  -> col group (4 cols)
    const int row0 = by * GB_M;

    ull acc2[4][4];                   // [row-pair][col]
#pragma unroll
    for (int rp = 0; rp < 4; rp++)
#pragma unroll
        for (int c = 0; c < 4; c++) acc2[rp][c] = 0ull;

    for (int k0 = 0; k0 < N_FEATURES; k0 += GB_K) {
#pragma unroll
        for (int t = tid; t < (GB_M * GB_K) / 4; t += 256) {
            int r = t >> 3;
            int c = (t & 7) << 2;
            float4 v = *(const float4*)&X[(row0 + r) * N_FEATURES + k0 + c];
            As[(c + 0) * GB_MPAD + r] = v.x;
            As[(c + 1) * GB_MPAD + r] = v.y;
            As[(c + 2) * GB_MPAD + r] = v.z;
            As[(c + 3) * GB_MPAD + r] = v.w;
        }
#pragma unroll
        for (int t = tid; t < (GB_K * GB_N) / 4; t += 256) {
            int r = t >> 5;
            int c = (t & 31) << 2;
            float4 v = *(const float4*)&W[(k0 + r) * ldw + ncol0 + c];
            *(float4*)&Bs[r * GB_N + c] = v;
        }
        __syncthreads();

#pragma unroll
        for (int k = 0; k < GB_K; k++) {
            const ull* arow = (const ull*)&As[k * GB_MPAD + ty * 8]; // broadcast LDS.64
            ull a2[4];
#pragma unroll
            for (int rp = 0; rp < 4; rp++) a2[rp] = arow[rp];
            float4 bv = *(const float4*)&Bs[k * GB_N + tx * 4];
            ull bd[4] = { pack2(bv.x, bv.x), pack2(bv.y, bv.y),
                          pack2(bv.z, bv.z), pack2(bv.w, bv.w) };
#pragma unroll
            for (int rp = 0; rp < 4; rp++)
#pragma unroll
                for (int c = 0; c < 4; c++) ffma2(acc2[rp][c], a2[rp], bd[c]);
        }
        __syncthreads();
    }

    const int col0 = bx * 128 + tx * 4;
#pragma unroll
    for (int rp = 0; rp < 4; rp++) {
        float2 p0 = unpack2(acc2[rp][0]);
        float2 p1 = unpack2(acc2[rp][1]);
        float2 p2 = unpack2(acc2[rp][2]);
        float2 p3 = unpack2(acc2[rp][3]);
        int re = row0 + ty * 8 + 2 * rp;
        *(float4*)&g_QKV[re * QKV_COLS + col0]       = make_float4(p0.x, p1.x, p2.x, p3.x);
        *(float4*)&g_QKV[(re + 1) * QKV_COLS + col0] = make_float4(p0.y, p1.y, p2.y, p3.y);
    }
}

// ---------------------------------------------------------------------------
// Kernel 3: score phase, row-split across SPLIT CTAs per graph.
// CTA (r, g): rows i with global-warp-id gw = r*8 + w, i = gw, gw+32, ...
// Each CTA writes its partial colsum to g_wpart[r][g][:] (no atomics).
// ---------------------------------------------------------------------------
#define SC_SMEM_FLOATS (NGMAX * KPAD + 8 * NGMAX + 8 * KEY_DIM)
#define SC_SMEM_BYTES  (SC_SMEM_FLOATS * 4)

__global__ __launch_bounds__(256)
void attn_score_kernel() {
    extern __shared__ float sm[];
    float* sK   = sm;                         // NGMAX * KPAD
    float* wcol = sK + NGMAX * KPAD;          // 8 * NGMAX (per-warp partials)
    float* sQ   = wcol + 8 * NGMAX;           // 8 * 128

    const int r    = blockIdx.x;              // 0..SPLIT-1
    const int g    = blockIdx.y;              // 0..191
    const int tid  = threadIdx.x;
    const int w    = tid >> 5;
    const int lane = tid & 31;
    const int gw   = r * 8 + w;               // 0..31 global warp within graph

    int s = g_start[g];
    int n = g_end[g] - s;
    if (n <= 0) return;                       // out kernel writes zeros
    if (n > NGMAX) n = NGMAX;                 // unreachable (mean 64, max ~95)

    // Stage K rows: float4 gmem reads, float2 smem stores
    for (int t = tid; t < n * (KEY_DIM / 4); t += 256) {
        int j = t >> 5;
        int k = (t & 31) << 2;
        float4 v = *(const float4*)&g_QKV[(s + j) * QKV_COLS + KEY_DIM + k];
        *(float2*)&sK[j * KPAD + k]     = make_float2(v.x, v.y);
        *(float2*)&sK[j * KPAD + k + 2] = make_float2(v.z, v.w);
    }
    for (int t = tid; t < 8 * NGMAX; t += 256) wcol[t] = 0.0f;
    __syncthreads();

    for (int i = gw; i < n; i += SPLIT * 8) {
        // stage Q row (128 floats = 32 lanes x float4)
        {
            float4 v = *(const float4*)&g_QKV[(s + i) * QKV_COLS + lane * 4];
            *(float4*)&sQ[w * KEY_DIM + lane * 4] = v;
        }
        __syncwarp();

        const ull* q2 = (const ull*)&sQ[w * KEY_DIM];
        float sc[(NGMAX + 31) / 32];
        float m = -INFINITY;
        int nj = 0;
        for (int j = lane; j < n; j += 32) {
            const ull* k2 = (const ull*)&sK[j * KPAD];
            ull a0 = 0, a1 = 0, a2v = 0, a3 = 0;
#pragma unroll
            for (int kk = 0; kk < KEY_DIM / 2; kk += 4) {
                ffma2(a0,  q2[kk + 0], k2[kk + 0]);
                ffma2(a1,  q2[kk + 1], k2[kk + 1]);
                ffma2(a2v, q2[kk + 2], k2[kk + 2]);
                ffma2(a3,  q2[kk + 3], k2[kk + 3]);
            }
            float2 t2 = unpack2(addx2(addx2(a0, a1), addx2(a2v, a3)));
            float d = (t2.x + t2.y) * 0.0625f;       // / sqrt(256)
            sc[nj++] = d;
            m = fmaxf(m, d);
        }
#pragma unroll
        for (int o = 16; o > 0; o >>= 1) m = fmaxf(m, __shfl_xor_sync(0xffffffffu, m, o));
        float ssum = 0.0f;
        for (int q = 0; q < nj; q++) { sc[q] = __expf(sc[q] - m); ssum += sc[q]; }
#pragma unroll
        for (int o = 16; o > 0; o >>= 1) ssum += __shfl_xor_sync(0xffffffffu, ssum, o);
        const float inv = 1.0f / ssum;
        nj = 0;
        for (int j = lane; j < n; j += 32) wcol[w * NGMAX + j] += sc[nj++] * inv;
        __syncwarp();                                // protect sQ before next row
    }
    __syncthreads();

    // Reduce this CTA's 8 warp-partials, write the split-partial (fixed order)
    for (int j = tid; j < n; j += 256) {
        float t = 0.0f;
#pragma unroll
        for (int ww = 0; ww < 8; ww++) t += wcol[ww * NGMAX + j];
        g_wpart[(r * N_GRAPHS + g) * NGMAX + j] = t;
    }
}

// ---------------------------------------------------------------------------
// Kernel 4: final reduce + weighted V sum. One CTA (256 thr) per graph.
//   w[j] = sum_r wpart[r][g][j]   (fixed order -> deterministic)
//   out[g, f] = sum_j w[j] * V[j, f]
// ---------------------------------------------------------------------------
__global__ __launch_bounds__(256)
void attn_out_kernel(float* __restrict__ out) {
    __shared__ float colsum[NGMAX];

    const int g   = blockIdx.x;
    const int tid = threadIdx.x;

    int s = g_start[g];
    int n = g_end[g] - s;
    if (n <= 0) {
        out[g * N_FEATURES + tid] = 0.0f;
        return;
    }
    if (n > NGMAX) n = NGMAX;

    if (tid < NGMAX) {
        int j = tid;
        float t = 0.0f;
        if (j < n) {
#pragma unroll
            for (int r = 0; r < SPLIT; r++)
                t += g_wpart[(r * N_GRAPHS + g) * NGMAX + j];
        }
        colsum[j] = t;
    }
    __syncthreads();

    // Weighted sum of V rows; thread = feature (coalesced 1KB rows), 4-way MLP
    const int f = tid;
    const float* Vb = &g_QKV[(size_t)s * QKV_COLS + 2 * KEY_DIM + f];
    float a0 = 0.0f, a1 = 0.0f, a2 = 0.0f, a3 = 0.0f;
    int j = 0;
    for (; j + 3 < n; j += 4) {
        a0 += colsum[j + 0] * Vb[(size_t)(j + 0) * QKV_COLS];
        a1 += colsum[j + 1] * Vb[(size_t)(j + 1) * QKV_COLS];
        a2 += colsum[j + 2] * Vb[(size_t)(j + 2) * QKV_COLS];
        a3 += colsum[j + 3] * Vb[(size_t)(j + 3) * QKV_COLS];
    }
    for (; j < n; j++) a0 += colsum[j] * Vb[(size_t)j * QKV_COLS];
    out[g * N_FEATURES + f] = (a0 + a1) + (a2 + a3);
}

// ---------------------------------------------------------------------------
// Launch
// ---------------------------------------------------------------------------
extern "C" void kernel_launch(void* const* d_in, const int* in_sizes, int n_in,
                              void* d_out, int out_size) {
    const float* X  = (const float*)d_in[0];
    const void*  batch = d_in[1];
    const float* Wq = (const float*)d_in[2];
    const float* Wk = (const float*)d_in[3];
    const float* Wv = (const float*)d_in[4];
    float* out = (float*)d_out;

    cudaFuncSetAttribute(attn_score_kernel,
                         cudaFuncAttributeMaxDynamicSharedMemorySize,
                         SC_SMEM_BYTES);

    init_ranges_kernel<<<1, N_GRAPHS>>>();
    compute_ranges_kernel<<<(N_NODES + 255) / 256, 256>>>(batch);
    qkv_gemm_kernel<<<dim3(4, N_NODES / GB_M), 256>>>(X, Wq, Wk, Wv);
    attn_score_kernel<<<dim3(SPLIT, N_GRAPHS), 256, SC_SMEM_BYTES>>>();
    attn_out_kernel<<<N_GRAPHS, 256>>>(out);
}